// round 10
// baseline (speedup 1.0000x reference)
#include <cuda_runtime.h>
#include <cuda_fp16.h>
#include <cstdint>
#include <cstddef>

#define NPIX 16384
#define CHN 128
#define BATCH 4
#define NSLICE 64

// ---------------- scratch (device globals; no allocation allowed) -------------
__device__ __align__(16) __half g_cath[BATCH * 8 * NPIX * 16];   // cat, fp16 interleaved
__device__ __align__(16) __half g_buf1h[BATCH * 8 * NPIX * 16];  // conv1 out, fp16 interleaved
__device__ float g_feat[BATCH * CHN * NPIX];          // 1x1 out, then feat (= unnormalized V)
__device__ float g_gpart[NSLICE * BATCH * CHN * CHN];
__device__ float g_G[BATCH * CHN * CHN];
__device__ float g_tpart[NSLICE * BATCH * CHN * 64];
__device__ float g_t2[BATCH * CHN * 64];
// fp16 conv weight fragments: [chunk8][tap9][mfrag8][lane32] uint4
__device__ uint32_t g_wh1[8 * 9 * 8 * 32 * 4];
__device__ uint32_t g_wh2[8 * 9 * 8 * 32 * 4];
__device__ uint32_t g_wih[8 * 8 * 32 * 4];            // 1x1 fp16 fragments

__device__ __forceinline__ float leakyf(float v) { return v >= 0.f ? v : 0.2f * v; }

__device__ __forceinline__ void mma_tf32(float* acc, const uint4& a, uint32_t b0, uint32_t b1) {
    asm volatile(
        "mma.sync.aligned.m16n8k8.row.col.f32.tf32.tf32.f32 "
        "{%0,%1,%2,%3}, {%4,%5,%6,%7}, {%8,%9}, {%0,%1,%2,%3};"
        : "+f"(acc[0]), "+f"(acc[1]), "+f"(acc[2]), "+f"(acc[3])
        : "r"(a.x), "r"(a.y), "r"(a.z), "r"(a.w), "r"(b0), "r"(b1));
}
__device__ __forceinline__ void mma_f16(float* acc, const uint4& a, uint32_t b0, uint32_t b1) {
    asm volatile(
        "mma.sync.aligned.m16n8k16.row.col.f32.f16.f16.f32 "
        "{%0,%1,%2,%3}, {%4,%5,%6,%7}, {%8,%9}, {%0,%1,%2,%3};"
        : "+f"(acc[0]), "+f"(acc[1]), "+f"(acc[2]), "+f"(acc[3])
        : "r"(a.x), "r"(a.y), "r"(a.z), "r"(a.w), "r"(b0), "r"(b1));
}

__device__ __forceinline__ uint32_t smem_u32(const void* p) {
    return (uint32_t)__cvta_generic_to_shared(p);
}
__device__ __forceinline__ void cp16(uint32_t s, const void* g) {
    asm volatile("cp.async.cg.shared.global [%0], [%1], 16;" :: "r"(s), "l"(g));
}
__device__ __forceinline__ void cp16z(uint32_t s, const void* g, int valid16) {
    asm volatile("cp.async.cg.shared.global [%0], [%1], 16, %2;"
                 :: "r"(s), "l"(g), "r"(valid16));
}
#define CP_COMMIT() asm volatile("cp.async.commit_group;")
#define CP_WAIT1() asm volatile("cp.async.wait_group 1;")
#define CP_WAIT0() asm volatile("cp.async.wait_group 0;")

__device__ __forceinline__ uint32_t pack_h2(float lo, float hi) {
    __half2 h = __floats2half2_rn(lo, hi);
    return *(uint32_t*)&h;
}
// permuted ic position inside 16-ic group (matches m16n8k16 B-fragment order)
__device__ __forceinline__ int icpos(int k) {
    return (k < 8) ? ((k >> 1) * 4 + (k & 1)) : (((k - 8) >> 1) * 4 + 2 + (k & 1));
}

// ---------------- prep + weight repack (single launch) ------------------------
__device__ __forceinline__ void repack_wh(const float* __restrict__ w, uint4* __restrict__ out,
                                          int idx)
{
    int lane = idx & 31;
    int t = idx >> 5;
    int mf = t & 7;
    int t2 = t >> 3;
    int tap = t2 % 9;
    int chunk = t2 / 9;
    int lq = lane >> 2, lr = lane & 3;
    int oc0 = mf * 16 + lq, oc1 = oc0 + 8;
    int kb = chunk * 16;
    uint4 o;
    o.x = pack_h2(w[((size_t)oc0 * CHN + kb + 2 * lr) * 9 + tap],
                  w[((size_t)oc0 * CHN + kb + 2 * lr + 1) * 9 + tap]);
    o.y = pack_h2(w[((size_t)oc1 * CHN + kb + 2 * lr) * 9 + tap],
                  w[((size_t)oc1 * CHN + kb + 2 * lr + 1) * 9 + tap]);
    o.z = pack_h2(w[((size_t)oc0 * CHN + kb + 8 + 2 * lr) * 9 + tap],
                  w[((size_t)oc0 * CHN + kb + 9 + 2 * lr) * 9 + tap]);
    o.w = pack_h2(w[((size_t)oc1 * CHN + kb + 8 + 2 * lr) * 9 + tap],
                  w[((size_t)oc1 * CHN + kb + 9 + 2 * lr) * 9 + tap]);
    out[idx] = o;
}

__global__ void prep_all_kernel(const float* __restrict__ x1, const float* __restrict__ x2,
                                const float* __restrict__ w1, const float* __restrict__ w2,
                                const float* __restrict__ wi,
                                uint32_t* __restrict__ wh1, uint32_t* __restrict__ wh2,
                                uint32_t* __restrict__ wih)
{
    int bx = blockIdx.x;
    if (bx < 8192) {
        int i4 = bx * 256 + threadIdx.x;
        if (i4 >= (BATCH * CHN * NPIX) / 4) return;
        size_t base = (size_t)i4 * 4;
        int b = (int)(base >> 21);
        int rem = (int)(base & ((1u << 21) - 1));
        int ic = rem >> 14;
        int n = rem & (NPIX - 1);
        const float* src = (ic < 64) ? x1 + ((size_t)(b * 64 + ic) << 14) + n
                                     : x2 + ((size_t)(b * 64 + ic - 64) << 14) + n;
        float4 v = *(const float4*)src;
        int chunk = ic >> 4;
        int ip = icpos(ic & 15);
        __half* hd = g_cath + (((size_t)(b * 8 + chunk) * NPIX + n) << 4) + ip;
        hd[0] = __float2half_rn(v.x);
        hd[16] = __float2half_rn(v.y);
        hd[32] = __float2half_rn(v.z);
        hd[48] = __float2half_rn(v.w);
    } else if (bx < 8264) {
        int idx = (bx - 8192) * 256 + threadIdx.x;
        if (idx < 18432) repack_wh(w1, (uint4*)wh1, idx);
    } else if (bx < 8336) {
        int idx = (bx - 8264) * 256 + threadIdx.x;
        if (idx < 18432) repack_wh(w2, (uint4*)wh2, idx);
    } else {
        int idx = (bx - 8336) * 256 + threadIdx.x;
        if (idx >= 2048) return;
        int lane = idx & 31;
        int t = idx >> 5;
        int mf = t & 7;
        int chunk = t >> 3;
        int lq = lane >> 2, lr = lane & 3;
        int oc0 = mf * 16 + lq, oc1 = oc0 + 8;
        int kb = chunk * 16;
        uint4 o;
        o.x = pack_h2(wi[(size_t)oc0 * CHN + kb + 2 * lr], wi[(size_t)oc0 * CHN + kb + 2 * lr + 1]);
        o.y = pack_h2(wi[(size_t)oc1 * CHN + kb + 2 * lr], wi[(size_t)oc1 * CHN + kb + 2 * lr + 1]);
        o.z = pack_h2(wi[(size_t)oc0 * CHN + kb + 8 + 2 * lr], wi[(size_t)oc0 * CHN + kb + 9 + 2 * lr]);
        o.w = pack_h2(wi[(size_t)oc1 * CHN + kb + 8 + 2 * lr], wi[(size_t)oc1 * CHN + kb + 9 + 2 * lr]);
        ((uint4*)wih)[idx] = o;
    }
}

// ---------------- conv 3x3 via fp16 m16n8k16, weights via direct LDG ---------
// CTA 256 thr (8 warps): 128 oc x 128 px (8 rows x 16 cols); 8 chunks of 16 ic.
// Input cp.async double-buffered; A fragments LDG-prefetched one tap ahead.
template <bool FIRST>
__global__ __launch_bounds__(256, 2) void conv_fp16_kernel(const float* __restrict__ bias)
{
    __shared__ __half sIn[2][2880];            // [10 rows][18 px][16 icperm]

    const int tid = threadIdx.x;
    const int lane = tid & 31;
    const int wid = tid >> 5;
    const int warpM = wid & 3;
    const int warpN = wid >> 2;
    const int lq = lane >> 2;
    const int lr = lane & 3;
    const int b = blockIdx.z;
    const int r0 = blockIdx.y * 8;
    const int c0 = blockIdx.x * 16;

    float acc[2][8][4];
#pragma unroll
    for (int m = 0; m < 2; m++)
#pragma unroll
        for (int j = 0; j < 8; j++)
#pragma unroll
            for (int e = 0; e < 4; e++) acc[m][j][e] = 0.f;

    const uint4* wsrc = (const uint4*)(FIRST ? g_wh1 : g_wh2);
    const uint4* wwarp0 = wsrc + (warpM * 2 + 0) * 32 + lane;   // + (cc*9+tap)*256
    const uint4* wwarp1 = wsrc + (warpM * 2 + 1) * 32 + lane;
    const __half* ibase = (FIRST ? g_cath : g_buf1h) + ((size_t)b * 8 * NPIX << 4);

    auto stin = [&](int buf, int cc) {
        const __half* src = ibase + ((size_t)cc * NPIX << 4);
        __half* dst = sIn[buf];
        for (int i = tid; i < 360; i += 256) {
            int row = i / 36;
            int p2 = i - row * 36;
            int px = p2 >> 1, hp = p2 & 1;
            int gr = r0 - 1 + row, gc = c0 - 1 + px;
            bool ok = ((unsigned)gr < 128u) && ((unsigned)gc < 128u);
            const __half* g = src + (((size_t)(ok ? gr * 128 + gc : 0)) << 4) + hp * 8;
            cp16z(smem_u32(dst + row * 288 + px * 16 + hp * 8), g, ok ? 16 : 0);
        }
    };

    stin(0, 0);
    CP_COMMIT();

    // prime A fragments for step 0
    uint4 a0 = __ldg(wwarp0);
    uint4 a1 = __ldg(wwarp1);

    for (int cc = 0; cc < 8; cc++) {
        if (cc < 7) {
            stin((cc + 1) & 1, cc + 1);
            CP_COMMIT();
            CP_WAIT1();
        } else {
            CP_WAIT0();
        }
        __syncthreads();

        const __half* ib = sIn[cc & 1];
#pragma unroll
        for (int tap = 0; tap < 9; tap++) {
            const int dr = tap / 3, dc = tap % 3;
            // batch-load all 8 B fragments for this tap
            uint2 bv[8];
#pragma unroll
            for (int j = 0; j < 8; j++) {
                int row = warpN * 4 + (j >> 1) + dr;
                int slot = (j & 1) * 8 + lq + dc;
                bv[j] = *(const uint2*)(ib + row * 288 + slot * 16 + lr * 4);
            }
            // prefetch next step's A fragments from L2
            int s = cc * 9 + tap;
            uint4 na0, na1;
            if (s < 71) {
                na0 = __ldg(wwarp0 + (s + 1) * 256);
                na1 = __ldg(wwarp1 + (s + 1) * 256);
            }
#pragma unroll
            for (int j = 0; j < 8; j++) {
                mma_f16(acc[0][j], a0, bv[j].x, bv[j].y);
                mma_f16(acc[1][j], a1, bv[j].x, bv[j].y);
            }
            if (s < 71) { a0 = na0; a1 = na1; }
        }
        __syncthreads();
    }

    // ---- epilogue ----
#pragma unroll
    for (int m = 0; m < 2; m++) {
        int oc = warpM * 32 + m * 16 + lq;
        float bv0 = bias[oc], bv1 = bias[oc + 8];
        if (FIRST) {
            const int chunk = warpM * 2 + m;
            const int ip0 = icpos(lq), ip1 = icpos(lq + 8);
            __half* hb = g_buf1h + (((size_t)(b * 8 + chunk) * NPIX) << 4);
#pragma unroll
            for (int j = 0; j < 8; j++) {
                int pix = (r0 + warpN * 4 + (j >> 1)) * 128 + c0 + (j & 1) * 8 + lr * 2;
                __half* p = hb + ((size_t)pix << 4);
                p[ip0] = __float2half_rn(leakyf(acc[m][j][0] + bv0));
                p[16 + ip0] = __float2half_rn(leakyf(acc[m][j][1] + bv0));
                p[ip1] = __float2half_rn(leakyf(acc[m][j][2] + bv1));
                p[16 + ip1] = __float2half_rn(leakyf(acc[m][j][3] + bv1));
            }
        } else {
#pragma unroll
            for (int j = 0; j < 8; j++) {
                int irow = r0 + warpN * 4 + (j >> 1);
                int icol = c0 + (j & 1) * 8 + lr * 2;
                size_t base0 = ((size_t)(b * CHN + oc) * 128 + irow) * 128 + icol;
                size_t base1 = base0 + (size_t)8 * NPIX;
                float2 p0 = *(const float2*)(g_feat + base0);
                float2 p1 = *(const float2*)(g_feat + base1);
                p0.x += leakyf(acc[m][j][0] + bv0);
                p0.y += leakyf(acc[m][j][1] + bv0);
                p1.x += leakyf(acc[m][j][2] + bv1);
                p1.y += leakyf(acc[m][j][3] + bv1);
                *(float2*)(g_feat + base0) = p0;
                *(float2*)(g_feat + base1) = p1;
            }
        }
    }
}

// ---------------- 1x1 conv via fp16 m16n8k16 (reuses g_cath) ------------------
__global__ __launch_bounds__(256) void gemm1x1h_kernel(const float* __restrict__ bi)
{
    __shared__ uint4 sW1[2][256];
    __shared__ __half sB[2][2048];   // [row8][px16][16icp]

    const int tid = threadIdx.x;
    const int lane = tid & 31;
    const int wid = tid >> 5;
    const int warpM = wid & 3;
    const int warpN = wid >> 2;
    const int lq = lane >> 2;
    const int lr = lane & 3;
    const int b = blockIdx.z;
    const int r0 = blockIdx.y * 8;
    const int c0 = blockIdx.x * 16;

    float acc[2][8][4];
#pragma unroll
    for (int m = 0; m < 2; m++)
#pragma unroll
        for (int j = 0; j < 8; j++)
#pragma unroll
            for (int e = 0; e < 4; e++) acc[m][j][e] = 0.f;

    const __half* ibase = g_cath + ((size_t)b * 8 * NPIX << 4);

    auto stage = [&](int buf, int cc) {
        int hp = tid & 1;
        int pl = tid >> 1;
        int row = pl >> 4, px = pl & 15;
        int pix = (r0 + row) * 128 + c0 + px;
        cp16(smem_u32(&sB[buf][(row * 16 + px) * 16 + hp * 8]),
             ibase + ((size_t)cc * NPIX << 4) + ((size_t)pix << 4) + hp * 8);
        cp16(smem_u32(&sW1[buf][tid]), ((const uint4*)g_wih) + cc * 256 + tid);
    };

    stage(0, 0);
    CP_COMMIT();

    for (int cc = 0; cc < 8; cc++) {
        if (cc < 7) {
            stage((cc + 1) & 1, cc + 1);
            CP_COMMIT();
            CP_WAIT1();
        } else {
            CP_WAIT0();
        }
        __syncthreads();

        uint4 a0 = sW1[cc & 1][(warpM * 2 + 0) * 32 + lane];
        uint4 a1 = sW1[cc & 1][(warpM * 2 + 1) * 32 + lane];
        const __half* ib = sB[cc & 1];
        uint2 bv[8];
#pragma unroll
        for (int j = 0; j < 8; j++) {
            int row = warpN * 4 + (j >> 1);
            int slot = (j & 1) * 8 + lq;
            bv[j] = *(const uint2*)(ib + (row * 16 + slot) * 16 + lr * 4);
        }
#pragma unroll
        for (int j = 0; j < 8; j++) {
            mma_f16(acc[0][j], a0, bv[j].x, bv[j].y);
            mma_f16(acc[1][j], a1, bv[j].x, bv[j].y);
        }
        __syncthreads();
    }

#pragma unroll
    for (int m = 0; m < 2; m++) {
        int oc = warpM * 32 + m * 16 + lq;
        float b0 = bi[oc], b1 = bi[oc + 8];
#pragma unroll
        for (int j = 0; j < 8; j++) {
            int irow = r0 + warpN * 4 + (j >> 1);
            int icol = c0 + (j & 1) * 8 + lr * 2;
            size_t base0 = ((size_t)(b * CHN + oc) * 128 + irow) * 128 + icol;
            size_t base1 = base0 + (size_t)8 * NPIX;
            *(float2*)(g_feat + base0) = make_float2(acc[m][j][0] + b0, acc[m][j][1] + b0);
            *(float2*)(g_feat + base1) = make_float2(acc[m][j][2] + b1, acc[m][j][3] + b1);
        }
    }
}

// ---------------- G = V V^T via tf32 mma, split-K -----------------------------
// (Projection is invariant to V row scaling, so the reference's L1
//  normalization cancels mathematically and is skipped.)
__global__ __launch_bounds__(256, 2) void gemmG_mma_kernel()
{
    __shared__ float sV[2][128 * 20];
    const int tid = threadIdx.x;
    const int lane = tid & 31;
    const int wid = tid >> 5;
    const int warpM = wid & 3;
    const int warpN = wid >> 2;
    const int lq = lane >> 2;
    const int lr = lane & 3;
    const int slice = blockIdx.x, b = blockIdx.y;
    const float* base = g_feat + (size_t)b * CHN * NPIX;
    const int k0g = slice * 256;

    float acc[2][8][4];
#pragma unroll
    for (int mi = 0; mi < 2; mi++)
#pragma unroll
        for (int nj = 0; nj < 8; nj++)
#pragma unroll
            for (int e = 0; e < 4; e++) acc[mi][nj][e] = 0.f;

    {
        int c = tid >> 1, q = tid & 1;
        cp16(smem_u32(&sV[0][c * 20 + q * 8]), base + (size_t)c * NPIX + k0g + q * 8);
        cp16(smem_u32(&sV[0][c * 20 + q * 8 + 4]), base + (size_t)c * NPIX + k0g + q * 8 + 4);
    }
    CP_COMMIT();

    for (int kc = 0; kc < 16; kc++) {
        if (kc < 15) {
            int c = tid >> 1, q = tid & 1;
            int kk = k0g + (kc + 1) * 16;
            cp16(smem_u32(&sV[(kc + 1) & 1][c * 20 + q * 8]), base + (size_t)c * NPIX + kk + q * 8);
            cp16(smem_u32(&sV[(kc + 1) & 1][c * 20 + q * 8 + 4]),
                 base + (size_t)c * NPIX + kk + q * 8 + 4);
            CP_COMMIT();
            CP_WAIT1();
        } else {
            CP_WAIT0();
        }
        __syncthreads();
        const float* sv = sV[kc & 1];
#pragma unroll
        for (int ks = 0; ks < 2; ks++) {
            int k = ks * 8;
            uint4 af[2];
#pragma unroll
            for (int mi = 0; mi < 2; mi++) {
                int m0 = warpM * 32 + mi * 16;
                af[mi].x = __float_as_uint(sv[(m0 + lq) * 20 + k + lr]);
                af[mi].y = __float_as_uint(sv[(m0 + lq + 8) * 20 + k + lr]);
                af[mi].z = __float_as_uint(sv[(m0 + lq) * 20 + k + lr + 4]);
                af[mi].w = __float_as_uint(sv[(m0 + lq + 8) * 20 + k + lr + 4]);
            }
#pragma unroll
            for (int nj = 0; nj < 8; nj++) {
                int n0 = warpN * 64 + nj * 8;
                uint32_t b0 = __float_as_uint(sv[(n0 + lq) * 20 + k + lr]);
                uint32_t b1 = __float_as_uint(sv[(n0 + lq) * 20 + k + lr + 4]);
                mma_tf32(acc[0][nj], af[0], b0, b1);
                mma_tf32(acc[1][nj], af[1], b0, b1);
            }
        }
        __syncthreads();
    }

    float* outp = g_gpart + ((size_t)slice * BATCH + b) * CHN * CHN;
#pragma unroll
    for (int mi = 0; mi < 2; mi++) {
        int m0 = warpM * 32 + mi * 16 + lq;
#pragma unroll
        for (int nj = 0; nj < 8; nj++) {
            int n = warpN * 64 + nj * 8 + lr * 2;
            *(float2*)(outp + m0 * 128 + n) = make_float2(acc[mi][nj][0], acc[mi][nj][1]);
            *(float2*)(outp + (m0 + 8) * 128 + n) = make_float2(acc[mi][nj][2], acc[mi][nj][3]);
        }
    }
}

__global__ void reduceG_kernel()
{
    int o = blockIdx.x * 256 + threadIdx.x;
    float s = 0.f;
    for (int sl = 0; sl < NSLICE; sl++)
        s += g_gpart[(size_t)sl * (BATCH * CHN * CHN) + o];
    g_G[o] = s;
}

// ---------------- t = V @ x1^T via tf32 mma, split-K --------------------------
__global__ __launch_bounds__(256, 2) void gemmT_mma_kernel(const float* __restrict__ x1)
{
    __shared__ float sV[2][128 * 20];
    __shared__ float sX[2][64 * 20];
    const int tid = threadIdx.x;
    const int lane = tid & 31;
    const int wid = tid >> 5;
    const int warpM = wid & 3;
    const int warpN = wid >> 2;
    const int lq = lane >> 2;
    const int lr = lane & 3;
    const int slice = blockIdx.x, b = blockIdx.y;
    const float* vbase = g_feat + (size_t)b * CHN * NPIX;
    const float* xbase = x1 + (size_t)b * 64 * NPIX;
    const int k0g = slice * 256;

    float acc[2][4][4];
#pragma unroll
    for (int mi = 0; mi < 2; mi++)
#pragma unroll
        for (int nj = 0; nj < 4; nj++)
#pragma unroll
            for (int e = 0; e < 4; e++) acc[mi][nj][e] = 0.f;

    auto stage = [&](int buf, int kc) {
        int kk = k0g + kc * 16;
        int c = tid >> 1, q = tid & 1;
        cp16(smem_u32(&sV[buf][c * 20 + q * 8]), vbase + (size_t)c * NPIX + kk + q * 8);
        cp16(smem_u32(&sV[buf][c * 20 + q * 8 + 4]), vbase + (size_t)c * NPIX + kk + q * 8 + 4);
        int m = tid >> 2, q2 = tid & 3;
        cp16(smem_u32(&sX[buf][m * 20 + q2 * 4]), xbase + (size_t)m * NPIX + kk + q2 * 4);
    };

    stage(0, 0);
    CP_COMMIT();

    for (int kc = 0; kc < 16; kc++) {
        if (kc < 15) {
            stage((kc + 1) & 1, kc + 1);
            CP_COMMIT();
            CP_WAIT1();
        } else {
            CP_WAIT0();
        }
        __syncthreads();
        const float* sv = sV[kc & 1];
        const float* sx = sX[kc & 1];
#pragma unroll
        for (int ks = 0; ks < 2; ks++) {
            int k = ks * 8;
            uint4 af[2];
#pragma unroll
            for (int mi = 0; mi < 2; mi++) {
                int m0 = warpM * 32 + mi * 16;
                af[mi].x = __float_as_uint(sv[(m0 + lq) * 20 + k + lr]);
                af[mi].y = __float_as_uint(sv[(m0 + lq + 8) * 20 + k + lr]);
                af[mi].z = __float_as_uint(sv[(m0 + lq) * 20 + k + lr + 4]);
                af[mi].w = __float_as_uint(sv[(m0 + lq + 8) * 20 + k + lr + 4]);
            }
#pragma unroll
            for (int nj = 0; nj < 4; nj++) {
                int n0 = warpN * 32 + nj * 8;
                uint32_t b0 = __float_as_uint(sx[(n0 + lq) * 20 + k + lr]);
                uint32_t b1 = __float_as_uint(sx[(n0 + lq) * 20 + k + lr + 4]);
                mma_tf32(acc[0][nj], af[0], b0, b1);
                mma_tf32(acc[1][nj], af[1], b0, b1);
            }
        }
        __syncthreads();
    }

    float* outp = g_tpart + ((size_t)slice * BATCH + b) * CHN * 64;
#pragma unroll
    for (int mi = 0; mi < 2; mi++) {
        int m0 = warpM * 32 + mi * 16 + lq;
#pragma unroll
        for (int nj = 0; nj < 4; nj++) {
            int n = warpN * 32 + nj * 8 + lr * 2;
            *(float2*)(outp + m0 * 64 + n) = make_float2(acc[mi][nj][0], acc[mi][nj][1]);
            *(float2*)(outp + (m0 + 8) * 64 + n) = make_float2(acc[mi][nj][2], acc[mi][nj][3]);
        }
    }
}

// ---------------- solve: [G | t] -> G^{-1} t, in shared memory ---------------
__global__ __launch_bounds__(768) void solve_kernel()
{
    extern __shared__ float sA[];  // [128][192]
    __shared__ float fcol[128];
    __shared__ float prow[192];
    const int b = blockIdx.x, tid = threadIdx.x;

    for (int i = tid; i < 128 * 128; i += 768) {
        int r = i >> 7, c = i & 127;
        sA[r * 192 + c] = g_G[(size_t)b * CHN * CHN + i];
    }
    for (int e = tid; e < 128 * 64; e += 768) {
        float s = 0.f;
        for (int sl = 0; sl < NSLICE; sl++)
            s += g_tpart[((size_t)sl * BATCH + b) * CHN * 64 + e];
        sA[(e >> 6) * 192 + 128 + (e & 63)] = s;
    }
    __syncthreads();

    const int j = tid % 192, g = tid / 192;
    for (int p = 0; p < 128; p++) {
        if (g == 0) {
            float piv = sA[p * 192 + p];
            prow[j] = sA[p * 192 + j] * (1.0f / piv);
        } else if (g == 1 && j < 128) {
            fcol[j] = (j == p) ? 0.f : sA[j * 192 + p];
        }
        __syncthreads();
        float pr = prow[j];
        const int i0 = g * 32;
#pragma unroll 4
        for (int i = i0; i < i0 + 32; i++) {
            float v = sA[i * 192 + j] - fcol[i] * pr;
            if (i == p) v = pr;
            sA[i * 192 + j] = v;
        }
        __syncthreads();
    }

    for (int e = tid; e < 128 * 64; e += 768)
        g_t2[(size_t)b * CHN * 64 + e] = sA[(e >> 6) * 192 + 128 + (e & 63)];
}

// ---------------- proj via tf32 mma -------------------------------------------
#define PROJ_SMEM (128 * 72 * 4 + 2 * 8 * 264 * 4)
__global__ __launch_bounds__(256, 2) void proj_mma_kernel(float* __restrict__ out)
{
    extern __shared__ float psm[];
    float* st2 = psm;                 // [128][72]
    float* sVc = psm + 128 * 72;      // [2][8][264]

    const int tid = threadIdx.x;
    const int lane = tid & 31;
    const int wid = tid >> 5;
    const int lq = lane >> 2;
    const int lr = lane & 3;
    const int b = blockIdx.y;
    const int n0cta = blockIdx.x * 256;
    const float* Vb = g_feat + (size_t)b * CHN * NPIX;

    {
        int e4 = tid;
        for (int i = 0; i < 8; i++, e4 += 256) {
            int c = e4 >> 4, mq = e4 & 15;
            cp16(smem_u32(st2 + c * 72 + mq * 4), g_t2 + (size_t)b * CHN * 64 + c * 64 + mq * 4);
        }
    }
    auto stageV = [&](int buf, int cc) {
        int r = tid >> 6, q = tid & 63;
        cp16(smem_u32(sVc + buf * 8 * 264 + r * 264 + q * 4),
             Vb + (size_t)(cc * 8 + r) * NPIX + n0cta + q * 4);
        cp16(smem_u32(sVc + buf * 8 * 264 + (r + 4) * 264 + q * 4),
             Vb + (size_t)(cc * 8 + r + 4) * NPIX + n0cta + q * 4);
    };
    stageV(0, 0);
    CP_COMMIT();

    float acc[4][4][4];
#pragma unroll
    for (int mi = 0; mi < 4; mi++)
#pragma unroll
        for (int nj = 0; nj < 4; nj++)
#pragma unroll
            for (int e = 0; e < 4; e++) acc[mi][nj][e] = 0.f;

    for (int cc = 0; cc < 16; cc++) {
        if (cc < 15) {
            stageV((cc + 1) & 1, cc + 1);
            CP_COMMIT();
            CP_WAIT1();
        } else {
            CP_WAIT0();
        }
        __syncthreads();
        const float* sv = sVc + (cc & 1) * 8 * 264;
        uint4 af[4];
#pragma unroll
        for (int mi = 0; mi < 4; mi++) {
            int m0 = mi * 16;
            int c0 = cc * 8;
            af[mi].x = __float_as_uint(st2[(c0 + lr) * 72 + m0 + lq]);
            af[mi].y = __float_as_uint(st2[(c0 + lr) * 72 + m0 + lq + 8]);
            af[mi].z = __float_as_uint(st2[(c0 + lr + 4) * 72 + m0 + lq]);
            af[mi].w = __float_as_uint(st2[(c0 + lr + 4) * 72 + m0 + lq + 8]);
        }
#pragma unroll
        for (int nj = 0; nj < 4; nj++) {
            int n0 = wid * 32 + nj * 8;
            uint32_t b0 = __float_as_uint(sv[lr * 264 + n0 + lq]);
            uint32_t b1 = __float_as_uint(sv[(lr + 4) * 264 + n0 + lq]);
#pragma unroll
            for (int mi = 0; mi < 4; mi++) mma_tf32(acc[mi][nj], af[mi], b0, b1);
        }
        __syncthreads();
    }

#pragma unroll
    for (int mi = 0; mi < 4; mi++) {
        int m0 = mi * 16 + lq;
#pragma unroll
        for (int nj = 0; nj < 4; nj++) {
            int n = n0cta + wid * 32 + nj * 8 + lr * 2;
            *(float2*)(out + ((size_t)(b * 64 + m0)) * NPIX + n) =
                make_float2(acc[mi][nj][0], acc[mi][nj][1]);
            *(float2*)(out + ((size_t)(b * 64 + m0 + 8)) * NPIX + n) =
                make_float2(acc[mi][nj][2], acc[mi][nj][3]);
        }
    }
}

// ---------------- launch -----------------------------------------------------
extern "C" void kernel_launch(void* const* d_in, const int* in_sizes, int n_in,
                              void* d_out, int out_size)
{
    const float* x1 = (const float*)d_in[0];
    const float* x2 = (const float*)d_in[1];
    const float* w1 = (const float*)d_in[2];
    const float* b1 = (const float*)d_in[3];
    const float* w2 = (const float*)d_in[4];
    const float* b2 = (const float*)d_in[5];
    const float* wi = (const float*)d_in[6];
    const float* bi = (const float*)d_in[7];
    float* out = (float*)d_out;

    static bool attr_done = false;
    if (!attr_done) {
        cudaFuncSetAttribute(solve_kernel, cudaFuncAttributeMaxDynamicSharedMemorySize,
                             128 * 192 * sizeof(float));
        cudaFuncSetAttribute(proj_mma_kernel,
                             cudaFuncAttributeMaxDynamicSharedMemorySize, PROJ_SMEM);
        attr_done = true;
    }

    uint32_t* wh1;  cudaGetSymbolAddress((void**)&wh1, g_wh1);
    uint32_t* wh2;  cudaGetSymbolAddress((void**)&wh2, g_wh2);
    uint32_t* wih;  cudaGetSymbolAddress((void**)&wih, g_wih);

    prep_all_kernel<<<8344, 256>>>(x1, x2, w1, w2, wi, wh1, wh2, wih);

    dim3 cgrid(8, 16, 4);
    conv_fp16_kernel<true><<<cgrid, 256>>>(b1);
    gemm1x1h_kernel<<<cgrid, 256>>>(bi);
    conv_fp16_kernel<false><<<cgrid, 256>>>(b2);

    gemmG_mma_kernel<<<dim3(NSLICE, BATCH), 256>>>();
    reduceG_kernel<<<256, 256>>>();
    gemmT_mma_kernel<<<dim3(NSLICE, BATCH), 256>>>(x1);
    solve_kernel<<<BATCH, 768, 128 * 192 * sizeof(float)>>>();
    proj_mma_kernel<<<dim3(64, BATCH), 256, PROJ_SMEM>>>(out);
}

// round 13
// speedup vs baseline: 1.1313x; 1.1313x over previous
#include <cuda_runtime.h>
#include <cuda_fp16.h>
#include <cstdint>
#include <cstddef>

#define NPIX 16384
#define CHN 128
#define BATCH 4
#define NSLICE 64

// ---------------- scratch (device globals; no allocation allowed) -------------
__device__ __align__(16) __half g_cath[BATCH * 8 * NPIX * 16];   // cat, fp16 interleaved
__device__ __align__(16) __half g_buf1h[BATCH * 8 * NPIX * 16];  // conv1 out, fp16 interleaved
__device__ float g_feat[BATCH * CHN * NPIX];          // 1x1 out, then feat (= unnormalized V)
__device__ float g_gpart[NSLICE * BATCH * CHN * CHN];
__device__ float g_G[BATCH * CHN * CHN];
__device__ float g_tpart[NSLICE * BATCH * CHN * 64];
__device__ float g_t[BATCH * CHN * 64];               // reduced t
__device__ float g_t2[BATCH * CHN * 64];              // G^{-1} t
// fp16 conv weight fragments: [chunk8][tap9][mfrag8][lane32] uint4
__device__ uint32_t g_wh1[8 * 9 * 8 * 32 * 4];
__device__ uint32_t g_wh2[8 * 9 * 8 * 32 * 4];
__device__ uint32_t g_wih[8 * 8 * 32 * 4];            // 1x1 fp16 fragments

__device__ __forceinline__ float leakyf(float v) { return v >= 0.f ? v : 0.2f * v; }

__device__ __forceinline__ void mma_tf32(float* acc, const uint4& a, uint32_t b0, uint32_t b1) {
    asm volatile(
        "mma.sync.aligned.m16n8k8.row.col.f32.tf32.tf32.f32 "
        "{%0,%1,%2,%3}, {%4,%5,%6,%7}, {%8,%9}, {%0,%1,%2,%3};"
        : "+f"(acc[0]), "+f"(acc[1]), "+f"(acc[2]), "+f"(acc[3])
        : "r"(a.x), "r"(a.y), "r"(a.z), "r"(a.w), "r"(b0), "r"(b1));
}
__device__ __forceinline__ void mma_f16(float* acc, const uint4& a, uint32_t b0, uint32_t b1) {
    asm volatile(
        "mma.sync.aligned.m16n8k16.row.col.f32.f16.f16.f32 "
        "{%0,%1,%2,%3}, {%4,%5,%6,%7}, {%8,%9}, {%0,%1,%2,%3};"
        : "+f"(acc[0]), "+f"(acc[1]), "+f"(acc[2]), "+f"(acc[3])
        : "r"(a.x), "r"(a.y), "r"(a.z), "r"(a.w), "r"(b0), "r"(b1));
}

__device__ __forceinline__ uint32_t smem_u32(const void* p) {
    return (uint32_t)__cvta_generic_to_shared(p);
}
__device__ __forceinline__ void cp16(uint32_t s, const void* g) {
    asm volatile("cp.async.cg.shared.global [%0], [%1], 16;" :: "r"(s), "l"(g));
}
__device__ __forceinline__ void cp16z(uint32_t s, const void* g, int valid16) {
    asm volatile("cp.async.cg.shared.global [%0], [%1], 16, %2;"
                 :: "r"(s), "l"(g), "r"(valid16));
}
#define CP_COMMIT() asm volatile("cp.async.commit_group;")
#define CP_WAIT1() asm volatile("cp.async.wait_group 1;")
#define CP_WAIT0() asm volatile("cp.async.wait_group 0;")

__device__ __forceinline__ uint32_t pack_h2(float lo, float hi) {
    __half2 h = __floats2half2_rn(lo, hi);
    return *(uint32_t*)&h;
}
// permuted ic position inside 16-ic group (matches m16n8k16 B-fragment order)
__device__ __forceinline__ int icpos(int k) {
    return (k < 8) ? ((k >> 1) * 4 + (k & 1)) : (((k - 8) >> 1) * 4 + 2 + (k & 1));
}

// ---------------- prep (smem transpose, coalesced) + weight repack ------------
__device__ __forceinline__ void repack_wh(const float* __restrict__ w, uint4* __restrict__ out,
                                          int idx)
{
    int lane = idx & 31;
    int t = idx >> 5;
    int mf = t & 7;
    int t2 = t >> 3;
    int tap = t2 % 9;
    int chunk = t2 / 9;
    int lq = lane >> 2, lr = lane & 3;
    int oc0 = mf * 16 + lq, oc1 = oc0 + 8;
    int kb = chunk * 16;
    uint4 o;
    o.x = pack_h2(w[((size_t)oc0 * CHN + kb + 2 * lr) * 9 + tap],
                  w[((size_t)oc0 * CHN + kb + 2 * lr + 1) * 9 + tap]);
    o.y = pack_h2(w[((size_t)oc1 * CHN + kb + 2 * lr) * 9 + tap],
                  w[((size_t)oc1 * CHN + kb + 2 * lr + 1) * 9 + tap]);
    o.z = pack_h2(w[((size_t)oc0 * CHN + kb + 8 + 2 * lr) * 9 + tap],
                  w[((size_t)oc0 * CHN + kb + 9 + 2 * lr) * 9 + tap]);
    o.w = pack_h2(w[((size_t)oc1 * CHN + kb + 8 + 2 * lr) * 9 + tap],
                  w[((size_t)oc1 * CHN + kb + 9 + 2 * lr) * 9 + tap]);
    out[idx] = o;
}

__global__ void prep_repack_kernel(const float* __restrict__ x1, const float* __restrict__ x2,
                                   const float* __restrict__ w1, const float* __restrict__ w2,
                                   const float* __restrict__ wi,
                                   uint32_t* __restrict__ wh1, uint32_t* __restrict__ wh2,
                                   uint32_t* __restrict__ wih)
{
    __shared__ __half sT[16][264];
    int bx = blockIdx.x;
    int tid = threadIdx.x;
    if (bx < 2048) {
        // transpose prep: block = batch b, chunk, 256 pixels
        int b = bx >> 9;
        int rem = bx & 511;
        int chunk = rem >> 6;
        int n0 = (rem & 63) * 256;
#pragma unroll
        for (int k = 0; k < 16; k++) {
            int ic = chunk * 16 + k;
            const float* src = (ic < 64) ? x1 + ((size_t)(b * 64 + ic) << 14)
                                         : x2 + ((size_t)(b * 64 + ic - 64) << 14);
            sT[k][tid] = __float2half_rn(src[n0 + tid]);
        }
        __syncthreads();
        __half v[16];
#pragma unroll
        for (int k = 0; k < 16; k++) v[icpos(k)] = sT[k][tid];
        __half* dst = g_cath + (((size_t)(b * 8 + chunk) * NPIX + n0 + tid) << 4);
        *(uint4*)dst = *(uint4*)&v[0];
        *(uint4*)(dst + 8) = *(uint4*)&v[8];
    } else if (bx < 2120) {
        int idx = (bx - 2048) * 256 + tid;
        if (idx < 18432) repack_wh(w1, (uint4*)wh1, idx);
    } else if (bx < 2192) {
        int idx = (bx - 2120) * 256 + tid;
        if (idx < 18432) repack_wh(w2, (uint4*)wh2, idx);
    } else {
        int idx = (bx - 2192) * 256 + tid;
        if (idx >= 2048) return;
        int lane = idx & 31;
        int t = idx >> 5;
        int mf = t & 7;
        int chunk = t >> 3;
        int lq = lane >> 2, lr = lane & 3;
        int oc0 = mf * 16 + lq, oc1 = oc0 + 8;
        int kb = chunk * 16;
        uint4 o;
        o.x = pack_h2(wi[(size_t)oc0 * CHN + kb + 2 * lr], wi[(size_t)oc0 * CHN + kb + 2 * lr + 1]);
        o.y = pack_h2(wi[(size_t)oc1 * CHN + kb + 2 * lr], wi[(size_t)oc1 * CHN + kb + 2 * lr + 1]);
        o.z = pack_h2(wi[(size_t)oc0 * CHN + kb + 8 + 2 * lr], wi[(size_t)oc0 * CHN + kb + 9 + 2 * lr]);
        o.w = pack_h2(wi[(size_t)oc1 * CHN + kb + 8 + 2 * lr], wi[(size_t)oc1 * CHN + kb + 9 + 2 * lr]);
        ((uint4*)wih)[idx] = o;
    }
}

// ---------------- conv 3x3 via fp16 m16n8k16, weights via direct LDG ---------
template <bool FIRST>
__global__ __launch_bounds__(256, 2) void conv_fp16_kernel(const float* __restrict__ bias)
{
    __shared__ __half sIn[2][2880];            // [10 rows][18 px][16 icperm]

    const int tid = threadIdx.x;
    const int lane = tid & 31;
    const int wid = tid >> 5;
    const int warpM = wid & 3;
    const int warpN = wid >> 2;
    const int lq = lane >> 2;
    const int lr = lane & 3;
    const int b = blockIdx.z;
    const int r0 = blockIdx.y * 8;
    const int c0 = blockIdx.x * 16;

    float acc[2][8][4];
#pragma unroll
    for (int m = 0; m < 2; m++)
#pragma unroll
        for (int j = 0; j < 8; j++)
#pragma unroll
            for (int e = 0; e < 4; e++) acc[m][j][e] = 0.f;

    const uint4* wsrc = (const uint4*)(FIRST ? g_wh1 : g_wh2);
    const uint4* wwarp0 = wsrc + (warpM * 2 + 0) * 32 + lane;   // + (cc*9+tap)*256
    const uint4* wwarp1 = wsrc + (warpM * 2 + 1) * 32 + lane;
    const __half* ibase = (FIRST ? g_cath : g_buf1h) + ((size_t)b * 8 * NPIX << 4);

    auto stin = [&](int buf, int cc) {
        const __half* src = ibase + ((size_t)cc * NPIX << 4);
        __half* dst = sIn[buf];
        for (int i = tid; i < 360; i += 256) {
            int row = i / 36;
            int p2 = i - row * 36;
            int px = p2 >> 1, hp = p2 & 1;
            int gr = r0 - 1 + row, gc = c0 - 1 + px;
            bool ok = ((unsigned)gr < 128u) && ((unsigned)gc < 128u);
            const __half* g = src + (((size_t)(ok ? gr * 128 + gc : 0)) << 4) + hp * 8;
            cp16z(smem_u32(dst + row * 288 + px * 16 + hp * 8), g, ok ? 16 : 0);
        }
    };

    stin(0, 0);
    CP_COMMIT();

    uint4 a0 = __ldg(wwarp0);
    uint4 a1 = __ldg(wwarp1);

    for (int cc = 0; cc < 8; cc++) {
        if (cc < 7) {
            stin((cc + 1) & 1, cc + 1);
            CP_COMMIT();
            CP_WAIT1();
        } else {
            CP_WAIT0();
        }
        __syncthreads();

        const __half* ib = sIn[cc & 1];
#pragma unroll
        for (int tap = 0; tap < 9; tap++) {
            const int dr = tap / 3, dc = tap % 3;
            uint2 bv[8];
#pragma unroll
            for (int j = 0; j < 8; j++) {
                int row = warpN * 4 + (j >> 1) + dr;
                int slot = (j & 1) * 8 + lq + dc;
                bv[j] = *(const uint2*)(ib + row * 288 + slot * 16 + lr * 4);
            }
            int s = cc * 9 + tap;
            uint4 na0, na1;
            if (s < 71) {
                na0 = __ldg(wwarp0 + (s + 1) * 256);
                na1 = __ldg(wwarp1 + (s + 1) * 256);
            }
#pragma unroll
            for (int j = 0; j < 8; j++) {
                mma_f16(acc[0][j], a0, bv[j].x, bv[j].y);
                mma_f16(acc[1][j], a1, bv[j].x, bv[j].y);
            }
            if (s < 71) { a0 = na0; a1 = na1; }
        }
        __syncthreads();
    }

    // ---- epilogue ----
#pragma unroll
    for (int m = 0; m < 2; m++) {
        int oc = warpM * 32 + m * 16 + lq;
        float bv0 = bias[oc], bv1 = bias[oc + 8];
        if (FIRST) {
            const int chunk = warpM * 2 + m;
            const int ip0 = icpos(lq), ip1 = icpos(lq + 8);
            __half* hb = g_buf1h + (((size_t)(b * 8 + chunk) * NPIX) << 4);
#pragma unroll
            for (int j = 0; j < 8; j++) {
                int pix = (r0 + warpN * 4 + (j >> 1)) * 128 + c0 + (j & 1) * 8 + lr * 2;
                __half* p = hb + ((size_t)pix << 4);
                p[ip0] = __float2half_rn(leakyf(acc[m][j][0] + bv0));
                p[16 + ip0] = __float2half_rn(leakyf(acc[m][j][1] + bv0));
                p[ip1] = __float2half_rn(leakyf(acc[m][j][2] + bv1));
                p[16 + ip1] = __float2half_rn(leakyf(acc[m][j][3] + bv1));
            }
        } else {
#pragma unroll
            for (int j = 0; j < 8; j++) {
                int irow = r0 + warpN * 4 + (j >> 1);
                int icol = c0 + (j & 1) * 8 + lr * 2;
                size_t base0 = ((size_t)(b * CHN + oc) * 128 + irow) * 128 + icol;
                size_t base1 = base0 + (size_t)8 * NPIX;
                float2 p0 = *(const float2*)(g_feat + base0);
                float2 p1 = *(const float2*)(g_feat + base1);
                p0.x += leakyf(acc[m][j][0] + bv0);
                p0.y += leakyf(acc[m][j][1] + bv0);
                p1.x += leakyf(acc[m][j][2] + bv1);
                p1.y += leakyf(acc[m][j][3] + bv1);
                *(float2*)(g_feat + base0) = p0;
                *(float2*)(g_feat + base1) = p1;
            }
        }
    }
}

// ---------------- 1x1 conv via fp16 m16n8k16 (reuses g_cath) ------------------
__global__ __launch_bounds__(256) void gemm1x1h_kernel(const float* __restrict__ bi)
{
    __shared__ uint4 sW1[2][256];
    __shared__ __half sB[2][2048];   // [row8][px16][16icp]

    const int tid = threadIdx.x;
    const int lane = tid & 31;
    const int wid = tid >> 5;
    const int warpM = wid & 3;
    const int warpN = wid >> 2;
    const int lq = lane >> 2;
    const int lr = lane & 3;
    const int b = blockIdx.z;
    const int r0 = blockIdx.y * 8;
    const int c0 = blockIdx.x * 16;

    float acc[2][8][4];
#pragma unroll
    for (int m = 0; m < 2; m++)
#pragma unroll
        for (int j = 0; j < 8; j++)
#pragma unroll
            for (int e = 0; e < 4; e++) acc[m][j][e] = 0.f;

    const __half* ibase = g_cath + ((size_t)b * 8 * NPIX << 4);

    auto stage = [&](int buf, int cc) {
        int hp = tid & 1;
        int pl = tid >> 1;
        int row = pl >> 4, px = pl & 15;
        int pix = (r0 + row) * 128 + c0 + px;
        cp16(smem_u32(&sB[buf][(row * 16 + px) * 16 + hp * 8]),
             ibase + ((size_t)cc * NPIX << 4) + ((size_t)pix << 4) + hp * 8);
        cp16(smem_u32(&sW1[buf][tid]), ((const uint4*)g_wih) + cc * 256 + tid);
    };

    stage(0, 0);
    CP_COMMIT();

    for (int cc = 0; cc < 8; cc++) {
        if (cc < 7) {
            stage((cc + 1) & 1, cc + 1);
            CP_COMMIT();
            CP_WAIT1();
        } else {
            CP_WAIT0();
        }
        __syncthreads();

        uint4 a0 = sW1[cc & 1][(warpM * 2 + 0) * 32 + lane];
        uint4 a1 = sW1[cc & 1][(warpM * 2 + 1) * 32 + lane];
        const __half* ib = sB[cc & 1];
        uint2 bv[8];
#pragma unroll
        for (int j = 0; j < 8; j++) {
            int row = warpN * 4 + (j >> 1);
            int slot = (j & 1) * 8 + lq;
            bv[j] = *(const uint2*)(ib + (row * 16 + slot) * 16 + lr * 4);
        }
#pragma unroll
        for (int j = 0; j < 8; j++) {
            mma_f16(acc[0][j], a0, bv[j].x, bv[j].y);
            mma_f16(acc[1][j], a1, bv[j].x, bv[j].y);
        }
        __syncthreads();
    }

#pragma unroll
    for (int m = 0; m < 2; m++) {
        int oc = warpM * 32 + m * 16 + lq;
        float b0 = bi[oc], b1 = bi[oc + 8];
#pragma unroll
        for (int j = 0; j < 8; j++) {
            int irow = r0 + warpN * 4 + (j >> 1);
            int icol = c0 + (j & 1) * 8 + lr * 2;
            size_t base0 = ((size_t)(b * CHN + oc) * 128 + irow) * 128 + icol;
            size_t base1 = base0 + (size_t)8 * NPIX;
            *(float2*)(g_feat + base0) = make_float2(acc[m][j][0] + b0, acc[m][j][1] + b0);
            *(float2*)(g_feat + base1) = make_float2(acc[m][j][2] + b1, acc[m][j][3] + b1);
        }
    }
}

// ---------------- G = V V^T via tf32 mma, split-K -----------------------------
// (Projection is invariant to V row scaling; reference's L1 normalization
//  cancels mathematically and is skipped.)
__global__ __launch_bounds__(256, 2) void gemmG_mma_kernel()
{
    __shared__ float sV[2][128 * 20];
    const int tid = threadIdx.x;
    const int lane = tid & 31;
    const int wid = tid >> 5;
    const int warpM = wid & 3;
    const int warpN = wid >> 2;
    const int lq = lane >> 2;
    const int lr = lane & 3;
    const int slice = blockIdx.x, b = blockIdx.y;
    const float* base = g_feat + (size_t)b * CHN * NPIX;
    const int k0g = slice * 256;

    float acc[2][8][4];
#pragma unroll
    for (int mi = 0; mi < 2; mi++)
#pragma unroll
        for (int nj = 0; nj < 8; nj++)
#pragma unroll
            for (int e = 0; e < 4; e++) acc[mi][nj][e] = 0.f;

    {
        int c = tid >> 1, q = tid & 1;
        cp16(smem_u32(&sV[0][c * 20 + q * 8]), base + (size_t)c * NPIX + k0g + q * 8);
        cp16(smem_u32(&sV[0][c * 20 + q * 8 + 4]), base + (size_t)c * NPIX + k0g + q * 8 + 4);
    }
    CP_COMMIT();

    for (int kc = 0; kc < 16; kc++) {
        if (kc < 15) {
            int c = tid >> 1, q = tid & 1;
            int kk = k0g + (kc + 1) * 16;
            cp16(smem_u32(&sV[(kc + 1) & 1][c * 20 + q * 8]), base + (size_t)c * NPIX + kk + q * 8);
            cp16(smem_u32(&sV[(kc + 1) & 1][c * 20 + q * 8 + 4]),
                 base + (size_t)c * NPIX + kk + q * 8 + 4);
            CP_COMMIT();
            CP_WAIT1();
        } else {
            CP_WAIT0();
        }
        __syncthreads();
        const float* sv = sV[kc & 1];
#pragma unroll
        for (int ks = 0; ks < 2; ks++) {
            int k = ks * 8;
            uint4 af[2];
#pragma unroll
            for (int mi = 0; mi < 2; mi++) {
                int m0 = warpM * 32 + mi * 16;
                af[mi].x = __float_as_uint(sv[(m0 + lq) * 20 + k + lr]);
                af[mi].y = __float_as_uint(sv[(m0 + lq + 8) * 20 + k + lr]);
                af[mi].z = __float_as_uint(sv[(m0 + lq) * 20 + k + lr + 4]);
                af[mi].w = __float_as_uint(sv[(m0 + lq + 8) * 20 + k + lr + 4]);
            }
#pragma unroll
            for (int nj = 0; nj < 8; nj++) {
                int n0 = warpN * 64 + nj * 8;
                uint32_t b0 = __float_as_uint(sv[(n0 + lq) * 20 + k + lr]);
                uint32_t b1 = __float_as_uint(sv[(n0 + lq) * 20 + k + lr + 4]);
                mma_tf32(acc[0][nj], af[0], b0, b1);
                mma_tf32(acc[1][nj], af[1], b0, b1);
            }
        }
        __syncthreads();
    }

    float* outp = g_gpart + ((size_t)slice * BATCH + b) * CHN * CHN;
#pragma unroll
    for (int mi = 0; mi < 2; mi++) {
        int m0 = warpM * 32 + mi * 16 + lq;
#pragma unroll
        for (int nj = 0; nj < 8; nj++) {
            int n = warpN * 64 + nj * 8 + lr * 2;
            *(float2*)(outp + m0 * 128 + n) = make_float2(acc[mi][nj][0], acc[mi][nj][1]);
            *(float2*)(outp + (m0 + 8) * 128 + n) = make_float2(acc[mi][nj][2], acc[mi][nj][3]);
        }
    }
}

// ---------------- reduce split-K partials for G and t -------------------------
__global__ void reduceGT_kernel()
{
    int o = blockIdx.x * 256 + threadIdx.x;
    if (o < BATCH * CHN * CHN) {
        float s = 0.f;
        for (int sl = 0; sl < NSLICE; sl++)
            s += g_gpart[(size_t)sl * (BATCH * CHN * CHN) + o];
        g_G[o] = s;
    } else {
        int e = o - BATCH * CHN * CHN;
        if (e >= BATCH * CHN * 64) return;
        int b = e >> 13, rem = e & 8191;
        float s = 0.f;
        for (int sl = 0; sl < NSLICE; sl++)
            s += g_tpart[((size_t)sl * BATCH + b) * CHN * 64 + rem];
        g_t[e] = s;
    }
}

// ---------------- t = V @ x1^T via tf32 mma, split-K --------------------------
__global__ __launch_bounds__(256, 2) void gemmT_mma_kernel(const float* __restrict__ x1)
{
    __shared__ float sV[2][128 * 20];
    __shared__ float sX[2][64 * 20];
    const int tid = threadIdx.x;
    const int lane = tid & 31;
    const int wid = tid >> 5;
    const int warpM = wid & 3;
    const int warpN = wid >> 2;
    const int lq = lane >> 2;
    const int lr = lane & 3;
    const int slice = blockIdx.x, b = blockIdx.y;
    const float* vbase = g_feat + (size_t)b * CHN * NPIX;
    const float* xbase = x1 + (size_t)b * 64 * NPIX;
    const int k0g = slice * 256;

    float acc[2][4][4];
#pragma unroll
    for (int mi = 0; mi < 2; mi++)
#pragma unroll
        for (int nj = 0; nj < 4; nj++)
#pragma unroll
            for (int e = 0; e < 4; e++) acc[mi][nj][e] = 0.f;

    auto stage = [&](int buf, int kc) {
        int kk = k0g + kc * 16;
        int c = tid >> 1, q = tid & 1;
        cp16(smem_u32(&sV[buf][c * 20 + q * 8]), vbase + (size_t)c * NPIX + kk + q * 8);
        cp16(smem_u32(&sV[buf][c * 20 + q * 8 + 4]), vbase + (size_t)c * NPIX + kk + q * 8 + 4);
        int m = tid >> 2, q2 = tid & 3;
        cp16(smem_u32(&sX[buf][m * 20 + q2 * 4]), xbase + (size_t)m * NPIX + kk + q2 * 4);
    };

    stage(0, 0);
    CP_COMMIT();

    for (int kc = 0; kc < 16; kc++) {
        if (kc < 15) {
            stage((kc + 1) & 1, kc + 1);
            CP_COMMIT();
            CP_WAIT1();
        } else {
            CP_WAIT0();
        }
        __syncthreads();
        const float* sv = sV[kc & 1];
        const float* sx = sX[kc & 1];
#pragma unroll
        for (int ks = 0; ks < 2; ks++) {
            int k = ks * 8;
            uint4 af[2];
#pragma unroll
            for (int mi = 0; mi < 2; mi++) {
                int m0 = warpM * 32 + mi * 16;
                af[mi].x = __float_as_uint(sv[(m0 + lq) * 20 + k + lr]);
                af[mi].y = __float_as_uint(sv[(m0 + lq + 8) * 20 + k + lr]);
                af[mi].z = __float_as_uint(sv[(m0 + lq) * 20 + k + lr + 4]);
                af[mi].w = __float_as_uint(sv[(m0 + lq + 8) * 20 + k + lr + 4]);
            }
#pragma unroll
            for (int nj = 0; nj < 4; nj++) {
                int n0 = warpN * 32 + nj * 8;
                uint32_t b0 = __float_as_uint(sx[(n0 + lq) * 20 + k + lr]);
                uint32_t b1 = __float_as_uint(sx[(n0 + lq) * 20 + k + lr + 4]);
                mma_tf32(acc[0][nj], af[0], b0, b1);
                mma_tf32(acc[1][nj], af[1], b0, b1);
            }
        }
        __syncthreads();
    }

    float* outp = g_tpart + ((size_t)slice * BATCH + b) * CHN * 64;
#pragma unroll
    for (int mi = 0; mi < 2; mi++) {
        int m0 = warpM * 32 + mi * 16 + lq;
#pragma unroll
        for (int nj = 0; nj < 4; nj++) {
            int n = warpN * 32 + nj * 8 + lr * 2;
            *(float2*)(outp + m0 * 64 + n) = make_float2(acc[mi][nj][0], acc[mi][nj][1]);
            *(float2*)(outp + (m0 + 8) * 64 + n) = make_float2(acc[mi][nj][2], acc[mi][nj][3]);
        }
    }
}

// ---------------- solve: [G | t] -> G^{-1} t, register-resident GJ -----------
// thread (g=tid/192, j=tid%192) owns A[g*32+i][j] in registers.
// Per pivot: col-p owners publish fcol, row-p owners publish prow; rank-1 update
// in registers. Dead G-columns (j <= p) skip updates; future pivots only read
// live columns. Same op order per live element as the smem version.
__global__ __launch_bounds__(768) void solve_kernel()
{
    __shared__ float fcol[128];
    __shared__ float prow[192];
    __shared__ float pinv_s;
    const int b = blockIdx.x, tid = threadIdx.x;
    const int j = tid % 192, g = tid / 192;

    float mv[32];
    if (j < 128) {
#pragma unroll
        for (int i = 0; i < 32; i++)
            mv[i] = g_G[(size_t)b * CHN * CHN + (size_t)(g * 32 + i) * 128 + j];
    } else {
        int m = j - 128;
#pragma unroll
        for (int i = 0; i < 32; i++)
            mv[i] = g_t[((size_t)b * CHN + g * 32 + i) * 64 + m];
    }

    for (int p = 0; p < 128; p++) {
        const int gp = p >> 5, pi = p & 31;
        if (j == p) {
#pragma unroll
            for (int i = 0; i < 32; i++) fcol[g * 32 + i] = mv[i];
            if (g == gp) pinv_s = 1.0f / mv[pi];
        }
        __syncthreads();
        if (g == gp) prow[j] = mv[pi] * pinv_s;
        __syncthreads();
        if (j >= 128 || j > p) {
            float pr = prow[j];
#pragma unroll
            for (int i = 0; i < 32; i++) {
                int row = g * 32 + i;
                float v = mv[i] - fcol[row] * pr;
                mv[i] = (row == p) ? pr : v;
            }
        }
        __syncthreads();
    }

    if (j >= 128) {
        int m = j - 128;
#pragma unroll
        for (int i = 0; i < 32; i++)
            g_t2[((size_t)b * CHN + g * 32 + i) * 64 + m] = mv[i];
    }
}

// ---------------- proj via tf32 mma -------------------------------------------
#define PROJ_SMEM (128 * 72 * 4 + 2 * 8 * 264 * 4)
__global__ __launch_bounds__(256, 2) void proj_mma_kernel(float* __restrict__ out)
{
    extern __shared__ float psm[];
    float* st2 = psm;                 // [128][72]
    float* sVc = psm + 128 * 72;      // [2][8][264]

    const int tid = threadIdx.x;
    const int lane = tid & 31;
    const int wid = tid >> 5;
    const int lq = lane >> 2;
    const int lr = lane & 3;
    const int b = blockIdx.y;
    const int n0cta = blockIdx.x * 256;
    const float* Vb = g_feat + (size_t)b * CHN * NPIX;

    {
        int e4 = tid;
        for (int i = 0; i < 8; i++, e4 += 256) {
            int c = e4 >> 4, mq = e4 & 15;
            cp16(smem_u32(st2 + c * 72 + mq * 4), g_t2 + (size_t)b * CHN * 64 + c * 64 + mq * 4);
        }
    }
    auto stageV = [&](int buf, int cc) {
        int r = tid >> 6, q = tid & 63;
        cp16(smem_u32(sVc + buf * 8 * 264 + r * 264 + q * 4),
             Vb + (size_t)(cc * 8 + r) * NPIX + n0cta + q * 4);
        cp16(smem_u32(sVc + buf * 8 * 264 + (r + 4) * 264 + q * 4),
             Vb + (size_t)(cc * 8 + r + 4) * NPIX + n0cta + q * 4);
    };
    stageV(0, 0);
    CP_COMMIT();

    float acc[4][4][4];
#pragma unroll
    for (int mi = 0; mi < 4; mi++)
#pragma unroll
        for (int nj = 0; nj < 4; nj++)
#pragma unroll
            for (int e = 0; e < 4; e++) acc[mi][nj][e] = 0.f;

    for (int cc = 0; cc < 16; cc++) {
        if (cc < 15) {
            stageV((cc + 1) & 1, cc + 1);
            CP_COMMIT();
            CP_WAIT1();
        } else {
            CP_WAIT0();
        }
        __syncthreads();
        const float* sv = sVc + (cc & 1) * 8 * 264;
        uint4 af[4];
#pragma unroll
        for (int mi = 0; mi < 4; mi++) {
            int m0 = mi * 16;
            int c0 = cc * 8;
            af[mi].x = __float_as_uint(st2[(c0 + lr) * 72 + m0 + lq]);
            af[mi].y = __float_as_uint(st2[(c0 + lr) * 72 + m0 + lq + 8]);
            af[mi].z = __float_as_uint(st2[(c0 + lr + 4) * 72 + m0 + lq]);
            af[mi].w = __float_as_uint(st2[(c0 + lr + 4) * 72 + m0 + lq + 8]);
        }
#pragma unroll
        for (int nj = 0; nj < 4; nj++) {
            int n0 = wid * 32 + nj * 8;
            uint32_t b0 = __float_as_uint(sv[lr * 264 + n0 + lq]);
            uint32_t b1 = __float_as_uint(sv[(lr + 4) * 264 + n0 + lq]);
#pragma unroll
            for (int mi = 0; mi < 4; mi++) mma_tf32(acc[mi][nj], af[mi], b0, b1);
        }
        __syncthreads();
    }

#pragma unroll
    for (int mi = 0; mi < 4; mi++) {
        int m0 = mi * 16 + lq;
#pragma unroll
        for (int nj = 0; nj < 4; nj++) {
            int n = n0cta + wid * 32 + nj * 8 + lr * 2;
            *(float2*)(out + ((size_t)(b * 64 + m0)) * NPIX + n) =
                make_float2(acc[mi][nj][0], acc[mi][nj][1]);
            *(float2*)(out + ((size_t)(b * 64 + m0 + 8)) * NPIX + n) =
                make_float2(acc[mi][nj][2], acc[mi][nj][3]);
        }
    }
}

// ---------------- launch -----------------------------------------------------
extern "C" void kernel_launch(void* const* d_in, const int* in_sizes, int n_in,
                              void* d_out, int out_size)
{
    const float* x1 = (const float*)d_in[0];
    const float* x2 = (const float*)d_in[1];
    const float* w1 = (const float*)d_in[2];
    const float* b1 = (const float*)d_in[3];
    const float* w2 = (const float*)d_in[4];
    const float* b2 = (const float*)d_in[5];
    const float* wi = (const float*)d_in[6];
    const float* bi = (const float*)d_in[7];
    float* out = (float*)d_out;

    static bool attr_done = false;
    if (!attr_done) {
        cudaFuncSetAttribute(proj_mma_kernel,
                             cudaFuncAttributeMaxDynamicSharedMemorySize, PROJ_SMEM);
        attr_done = true;
    }

    uint32_t* wh1;  cudaGetSymbolAddress((void**)&wh1, g_wh1);
    uint32_t* wh2;  cudaGetSymbolAddress((void**)&wh2, g_wh2);
    uint32_t* wih;  cudaGetSymbolAddress((void**)&wih, g_wih);

    prep_repack_kernel<<<2200, 256>>>(x1, x2, w1, w2, wi, wh1, wh2, wih);

    dim3 cgrid(8, 16, 4);
    conv_fp16_kernel<true><<<cgrid, 256>>>(b1);
    gemm1x1h_kernel<<<cgrid, 256>>>(bi);
    conv_fp16_kernel<false><<<cgrid, 256>>>(b2);

    gemmG_mma_kernel<<<dim3(NSLICE, BATCH), 256>>>();
    gemmT_mma_kernel<<<dim3(NSLICE, BATCH), 256>>>(x1);
    reduceGT_kernel<<<384, 256>>>();
    solve_kernel<<<BATCH, 768>>>();
    proj_mma_kernel<<<dim3(64, BATCH), 256, PROJ_SMEM>>>(out);
}